// round 9
// baseline (speedup 1.0000x reference)
#include <cuda_runtime.h>
#include <cuda_fp16.h>
#include <math.h>

#define NN 8192
#define NB 32
#define NG 256
#define NE 65536
#define DK 512
#define HH 32
#define VB 2048
#define VF 512
#define EPS 1e-5f

// ---------------- device scratch ----------------
__device__ float g_sB[NN], g_sF[NN];
__device__ __half2 g_vnB[NN * VB / 2];   // normalized visual_body fp16 (32 MB)
__device__ __half2 g_vnF[NN * VF / 2];   // normalized visual_face fp16 (8 MB)
__device__ float g_P0[DK], g_P1[DK];
__device__ float g_M1[DK], g_M2[DK], g_M3[DK];
__device__ float g_cst[12];
// sync state (reset by last block each launch)
__device__ int g_flag0 = 0;
__device__ int g_fNB[1024];
__device__ int g_fNF[1024];
__device__ int g_fA[1024];
__device__ int g_done = 0;

__device__ __forceinline__ float warpSum(float v) {
    #pragma unroll
    for (int o = 16; o; o >>= 1) v += __shfl_xor_sync(0xFFFFFFFFu, v, o);
    return v;
}

__device__ __forceinline__ int vload(const int* p) {
    return *(const volatile int*)p;
}

// ---------------- grid layout (256 threads per block) ----------------
// 0                      : precompute constants -> g_flag0
// [1, 1+1024)            : attention+node (spin g_flag0), publish g_fA
// [1025, 1025+1024)      : body norm, publish g_fNB
// [2049, 2049+1024)      : face norm, publish g_fNF
// [3073, 3073+8192)      : body edges (warp/edge, spin 4 flags)
// [11265, 11265+4096)    : face edges (half-warp/edge, spin flags)
#define BLK_PRE   0
#define BLK_ATTN  1
#define BLK_NB    (BLK_ATTN + 1024)
#define BLK_NF    (BLK_NB + 1024)
#define BLK_EB    (BLK_NF + 1024)
#define BLK_EF    (BLK_EB + 8192)
#define GRID_TOTAL (BLK_EF + 4096)

__global__ __launch_bounds__(256)
void mega_kernel(const float* __restrict__ visB, const float* __restrict__ visF,
                 const float* __restrict__ x,
                 const float* __restrict__ ln_g, const float* __restrict__ ln_b,
                 const float* __restrict__ prelu_a,
                 const float* __restrict__ Wq, const float* __restrict__ Wk,
                 const float* __restrict__ Wv,
                 const float* __restrict__ mlp_W, const float* __restrict__ mlp_b,
                 const float* __restrict__ np_W, const float* __restrict__ np_b,
                 const float* __restrict__ body_W, const float* __restrict__ body_b,
                 const float* __restrict__ face_W, const float* __restrict__ face_b,
                 const float* __restrict__ pb_W, const float* __restrict__ pb_b,
                 const float* __restrict__ pf_W, const float* __restrict__ pf_b,
                 const int* __restrict__ eiB, const int* __restrict__ eiF,
                 float* __restrict__ out) {
    int b = blockIdx.x;
    int t = threadIdx.x;
    int lane = t & 31;
    int warp = t >> 5;

    int my_flag_idx = -1;       // producer flag to publish in epilogue
    int* my_flag_arr = 0;

    if (b == BLK_PRE) {
        // ---------------- precompute constants (256 threads, 2 dims each) ----------------
        __shared__ float sh_u2[HH], sh_u3[HH], sh_np[HH];
        __shared__ float sh_part[8][9];
        __shared__ float sh_res[12];
        int k1 = t, k2 = t + 256;

        if (t < HH) {
            float a2 = 0.f, a3 = 0.f;
            #pragma unroll
            for (int j = 0; j < HH; ++j) {
                a2 += body_W[t * HH + j] * pb_W[j];
                a3 += face_W[t * HH + j] * pf_W[j];
            }
            sh_u2[t] = a2;
            sh_u3[t] = a3;
            sh_np[t] = np_W[t];
        }

        float wq0a = Wq[k1], wq0b = Wq[k2], wq1a = Wq[DK + k1], wq1b = Wq[DK + k2];
        float wk0a = Wk[k1], wk0b = Wk[k2], wk1a = Wk[DK + k1], wk1b = Wk[DK + k2];
        float wv0a = Wv[k1], wv0b = Wv[k2], wv1a = Wv[DK + k1], wv1b = Wv[DK + k2];

        float v0 = warpSum(wq0a * wk0a + wq0b * wk0b);
        float v1 = warpSum(wq0a * wk1a + wq0b * wk1b);
        float v2 = warpSum(wq1a * wk0a + wq1b * wk0b);
        float v3 = warpSum(wq1a * wk1a + wq1b * wk1b);
        float v4 = warpSum(wv0a + wv0b);
        float v5 = warpSum(wv1a + wv1b);
        float v6 = warpSum(wv0a * wv0a + wv0b * wv0b);
        float v7 = warpSum(wv0a * wv1a + wv0b * wv1b);
        float v8 = warpSum(wv1a * wv1a + wv1b * wv1b);
        if (lane == 0) {
            sh_part[warp][0] = v0; sh_part[warp][1] = v1; sh_part[warp][2] = v2;
            sh_part[warp][3] = v3; sh_part[warp][4] = v4; sh_part[warp][5] = v5;
            sh_part[warp][6] = v6; sh_part[warp][7] = v7; sh_part[warp][8] = v8;
        }
        __syncthreads();

        if (warp == 0) {
            float mb = mlp_b[lane];
            float b1 = warpSum(mb * sh_np[lane]);
            float b2 = warpSum(mb * sh_u2[lane]);
            float b3 = warpSum(mb * sh_u3[lane]);
            float vBv = warpSum(body_b[lane] * pb_W[lane]);
            float vFv = warpSum(face_b[lane] * pf_W[lane]);
            if (lane == 0) {
                float r[9];
                #pragma unroll
                for (int i = 0; i < 9; ++i) {
                    float s = 0.f;
                    #pragma unroll
                    for (int w = 0; w < 8; ++w) s += sh_part[w][i];
                    r[i] = s;
                }
                float m0 = r[4] / (float)DK, m1 = r[5] / (float)DK;
                sh_res[0] = r[0]; sh_res[1] = r[1]; sh_res[2] = r[2]; sh_res[3] = r[3];
                sh_res[4] = r[6] / (float)DK - m0 * m0;
                sh_res[5] = r[7] / (float)DK - m0 * m1;
                sh_res[6] = r[8] / (float)DK - m1 * m1;
                sh_res[7] = b1 + np_b[0] + pb_b[0] + pf_b[0];
                sh_res[8] = b2 + vBv;
                sh_res[9] = b3 + vFv;
                sh_res[10] = m0;
                sh_res[11] = m1;
            }
        }
        __syncthreads();

        if (t < 12) g_cst[t] = sh_res[t];
        g_P0[k1] = wv0a - sh_res[10];
        g_P0[k2] = wv0b - sh_res[10];
        g_P1[k1] = wv1a - sh_res[11];
        g_P1[k2] = wv1b - sh_res[11];

        float a1a = 0.f, a2a = 0.f, a3a = 0.f, a1b = 0.f, a2b = 0.f, a3b = 0.f;
        #pragma unroll
        for (int l = 0; l < HH; ++l) {
            float wa = mlp_W[k1 * HH + l];
            float wb = mlp_W[k2 * HH + l];
            float un = sh_np[l], u2 = sh_u2[l], u3 = sh_u3[l];
            a1a += wa * un; a2a += wa * u2; a3a += wa * u3;
            a1b += wb * un; a2b += wb * u2; a3b += wb * u3;
        }
        g_M1[k1] = a1a; g_M2[k1] = a2a; g_M3[k1] = a3a;
        g_M1[k2] = a1b; g_M2[k2] = a2b; g_M3[k2] = a3b;

        my_flag_arr = &g_flag0;
        my_flag_idx = 0;
    } else if (b < BLK_NB) {
        // ---------------- attention + node stage ----------------
        __shared__ float sa[NG], sb[NG];
        int idx = b - BLK_ATTN;          // 0..1023
        int g = idx >> 5;
        int bi = idx & 31;
        int node = g * NG + t;
        sa[t] = x[2 * node];
        sb[t] = x[2 * node + 1];
        if (t == 0) {
            while (vload(&g_flag0) == 0) __nanosleep(32);
        }
        __syncthreads();
        __threadfence();

        float g00 = g_cst[0], g01 = g_cst[1], g10 = g_cst[2], g11 = g_cst[3];
        const float inv = 0.04419417382415922f;
        int i = bi * 8 + warp;

        float ai = sa[i], bi2 = sb[i];
        float alpha = (ai * g00 + bi2 * g10) * inv;
        float beta  = (ai * g01 + bi2 * g11) * inv;
        float m = -1e30f;
        #pragma unroll
        for (int j = lane; j < NG; j += 32)
            m = fmaxf(m, alpha * sa[j] + beta * sb[j]);
        #pragma unroll
        for (int o = 16; o; o >>= 1) m = fmaxf(m, __shfl_xor_sync(0xFFFFFFFFu, m, o));
        float s = 0.f, sA = 0.f, sBv = 0.f;
        #pragma unroll
        for (int j = lane; j < NG; j += 32) {
            float e = __expf(alpha * sa[j] + beta * sb[j] - m);
            s += e; sA += e * sa[j]; sBv += e * sb[j];
        }
        s = warpSum(s); sA = warpSum(sA); sBv = warpSum(sBv);
        float c = sA / s, d = sBv / s;

        float s00 = g_cst[4], s01 = g_cst[5], s11 = g_cst[6];
        float var = c * c * s00 + 2.f * c * d * s01 + d * d * s11;
        float rstd = rsqrtf(var + EPS);
        float a = prelu_a[0];
        float acc1 = 0.f, acc2 = 0.f, acc3 = 0.f;
        #pragma unroll
        for (int k = lane; k < DK; k += 32) {
            float z = (c * g_P0[k] + d * g_P1[k]) * rstd;
            float tv = z * ln_g[k] + ln_b[k];
            tv = tv >= 0.f ? tv : a * tv;
            acc1 += tv * g_M1[k];
            acc2 += tv * g_M2[k];
            acc3 += tv * g_M3[k];
        }
        acc1 = warpSum(acc1); acc2 = warpSum(acc2); acc3 = warpSum(acc3);
        if (lane == 0) {
            int n = g * NG + i;
            out[n]  = acc1 + g_cst[7];
            g_sB[n] = acc2 + g_cst[8];
            g_sF[n] = acc3 + g_cst[9];
        }
        my_flag_arr = g_fA;
        my_flag_idx = idx;               // covers nodes idx*8 .. idx*8+7
    } else if (b < BLK_NF) {
        // ---------------- body norm: warp per row ----------------
        int nb = b - BLK_NB;             // 0..1023
        int row = nb * 8 + warp;
        const float4* v = reinterpret_cast<const float4*>(visB) + (size_t)row * (VB / 4) + lane;
        float4 r[16];
        #pragma unroll
        for (int i = 0; i < 16; ++i) r[i] = v[i * 32];
        float acc = 0.f;
        #pragma unroll
        for (int i = 0; i < 16; ++i)
            acc += r[i].x * r[i].x + r[i].y * r[i].y + r[i].z * r[i].z + r[i].w * r[i].w;
        acc = warpSum(acc);
        float rs = rsqrtf(acc + 1e-8f);
        uint2* o = reinterpret_cast<uint2*>(g_vnB) + (size_t)row * (VB / 4) + lane;
        #pragma unroll
        for (int i = 0; i < 16; ++i) {
            __half2 h0 = __floats2half2_rn(r[i].x * rs, r[i].y * rs);
            __half2 h1 = __floats2half2_rn(r[i].z * rs, r[i].w * rs);
            uint2 u;
            u.x = *reinterpret_cast<unsigned*>(&h0);
            u.y = *reinterpret_cast<unsigned*>(&h1);
            o[i * 32] = u;
        }
        my_flag_arr = g_fNB;
        my_flag_idx = nb;                // covers rows nb*8 .. nb*8+7
    } else if (b < BLK_EB) {
        // ---------------- face norm: warp per row ----------------
        int nf = b - BLK_NF;             // 0..1023
        int row = nf * 8 + warp;
        const float4* v = reinterpret_cast<const float4*>(visF) + (size_t)row * (VF / 4) + lane;
        float4 r[4];
        #pragma unroll
        for (int i = 0; i < 4; ++i) r[i] = v[i * 32];
        float acc = 0.f;
        #pragma unroll
        for (int i = 0; i < 4; ++i)
            acc += r[i].x * r[i].x + r[i].y * r[i].y + r[i].z * r[i].z + r[i].w * r[i].w;
        acc = warpSum(acc);
        float rs = rsqrtf(acc + 1e-8f);
        uint2* o = reinterpret_cast<uint2*>(g_vnF) + (size_t)row * (VF / 4) + lane;
        #pragma unroll
        for (int i = 0; i < 4; ++i) {
            __half2 h0 = __floats2half2_rn(r[i].x * rs, r[i].y * rs);
            __half2 h1 = __floats2half2_rn(r[i].z * rs, r[i].w * rs);
            uint2 u;
            u.x = *reinterpret_cast<unsigned*>(&h0);
            u.y = *reinterpret_cast<unsigned*>(&h1);
            o[i * 32] = u;
        }
        my_flag_arr = g_fNF;
        my_flag_idx = nf;
    } else if (b < BLK_EF) {
        // ---------------- body edges: warp per edge ----------------
        int e = (b - BLK_EB) * 8 + warp;
        int src = eiB[e], dst = eiB[NE + e];
        // wait for producers of vn[src], vn[dst], out[dst], s[src]
        {
            const int* f0 = &g_fNB[src >> 3];
            const int* f1 = &g_fNB[dst >> 3];
            const int* f2 = &g_fA[src >> 3];
            const int* f3 = &g_fA[dst >> 3];
            while (!(vload(f0) & vload(f1) & vload(f2) & vload(f3))) __nanosleep(64);
            __threadfence();
        }
        const int4* a = reinterpret_cast<const int4*>(g_vnB) + (size_t)src * (VB / 8) + lane;
        const int4* bb = reinterpret_cast<const int4*>(g_vnB) + (size_t)dst * (VB / 8) + lane;
        int4 ra[8], rb[8];
        #pragma unroll
        for (int i = 0; i < 8; ++i) ra[i] = a[i * 32];
        #pragma unroll
        for (int i = 0; i < 8; ++i) rb[i] = bb[i * 32];
        float acc0 = 0.f, acc1 = 0.f;
        #pragma unroll
        for (int i = 0; i < 8; ++i) {
            const __half2* ha = reinterpret_cast<const __half2*>(&ra[i]);
            const __half2* hb = reinterpret_cast<const __half2*>(&rb[i]);
            #pragma unroll
            for (int u = 0; u < 4; ++u) {
                float2 fa = __half22float2(ha[u]);
                float2 fb = __half22float2(hb[u]);
                acc0 += fa.x * fb.x;
                acc1 += fa.y * fb.y;
            }
        }
        float acc = warpSum(acc0 + acc1);
        if (lane == 0) atomicAdd(&out[dst], acc * g_sB[src]);
    } else {
        // ---------------- face edges: half-warp per edge ----------------
        int fw = (b - BLK_EF) * 8 + warp;
        int e = fw * 2 + (lane >> 4);
        int hl = lane & 15;
        int src = eiF[e], dst = eiF[NE + e];
        {
            const int* f0 = &g_fNF[src >> 3];
            const int* f1 = &g_fNF[dst >> 3];
            const int* f2 = &g_fA[src >> 3];
            const int* f3 = &g_fA[dst >> 3];
            while (true) {
                int ok = vload(f0) & vload(f1) & vload(f2) & vload(f3);
                if (__all_sync(0xFFFFFFFFu, ok)) break;
                __nanosleep(64);
            }
            __threadfence();
        }
        const int4* a = reinterpret_cast<const int4*>(g_vnF) + (size_t)src * (VF / 8) + hl;
        const int4* bb = reinterpret_cast<const int4*>(g_vnF) + (size_t)dst * (VF / 8) + hl;
        int4 ra[4], rb[4];
        #pragma unroll
        for (int i = 0; i < 4; ++i) ra[i] = a[i * 16];
        #pragma unroll
        for (int i = 0; i < 4; ++i) rb[i] = bb[i * 16];
        float acc0 = 0.f, acc1 = 0.f;
        #pragma unroll
        for (int i = 0; i < 4; ++i) {
            const __half2* ha = reinterpret_cast<const __half2*>(&ra[i]);
            const __half2* hb = reinterpret_cast<const __half2*>(&rb[i]);
            #pragma unroll
            for (int u = 0; u < 4; ++u) {
                float2 fa = __half22float2(ha[u]);
                float2 fb = __half22float2(hb[u]);
                acc0 += fa.x * fb.x;
                acc1 += fa.y * fb.y;
            }
        }
        float acc = acc0 + acc1;
        #pragma unroll
        for (int o = 8; o; o >>= 1) acc += __shfl_xor_sync(0xFFFFFFFFu, acc, o);
        if (hl == 0) atomicAdd(&out[dst], acc * g_sF[src]);
    }

    // ---------------- epilogue: publish flag, done counter, last block resets ----------------
    __shared__ int sh_last;
    __threadfence();
    __syncthreads();
    if (t == 0) {
        if (my_flag_idx >= 0) {
            *(volatile int*)&my_flag_arr[my_flag_idx] = 1;   // release (fenced above)
        }
        int d = atomicAdd(&g_done, 1);
        sh_last = (d == GRID_TOTAL - 1) ? 1 : 0;
    }
    __syncthreads();
    if (sh_last) {
        for (int i = t; i < 1024; i += 256) {
            g_fNB[i] = 0;
            g_fNF[i] = 0;
            g_fA[i] = 0;
        }
        if (t == 0) {
            g_flag0 = 0;
            __threadfence();
            g_done = 0;
        }
    }
}

// ---------------- launch ----------------
extern "C" void kernel_launch(void* const* d_in, const int* in_sizes, int n_in,
                              void* d_out, int out_size) {
    const float* x           = (const float*)d_in[0];
    const float* visual_body = (const float*)d_in[1];
    const float* visual_face = (const float*)d_in[2];
    const float* Wq          = (const float*)d_in[3];
    const float* Wk          = (const float*)d_in[4];
    const float* Wv          = (const float*)d_in[5];
    const float* ln_g        = (const float*)d_in[6];
    const float* ln_b        = (const float*)d_in[7];
    const float* prelu_a     = (const float*)d_in[8];
    const float* mlp_W       = (const float*)d_in[9];
    const float* mlp_b       = (const float*)d_in[10];
    const float* np_W        = (const float*)d_in[11];
    const float* np_b        = (const float*)d_in[12];
    const float* body_W      = (const float*)d_in[13];
    const float* body_b      = (const float*)d_in[14];
    const float* face_W      = (const float*)d_in[15];
    const float* face_b      = (const float*)d_in[16];
    const float* pb_W        = (const float*)d_in[17];
    const float* pb_b        = (const float*)d_in[18];
    const float* pf_W        = (const float*)d_in[19];
    const float* pf_b        = (const float*)d_in[20];
    const int*   ei_body     = (const int*)d_in[21];
    const int*   ei_face     = (const int*)d_in[22];
    float* out = (float*)d_out;

    mega_kernel<<<GRID_TOTAL, 256>>>(
        visual_body, visual_face, x, ln_g, ln_b, prelu_a,
        Wq, Wk, Wv, mlp_W, mlp_b, np_W, np_b,
        body_W, body_b, face_W, face_b, pb_W, pb_b, pf_W, pf_b,
        ei_body, ei_face, out);
}

// round 10
// speedup vs baseline: 1.3366x; 1.3366x over previous
#include <cuda_runtime.h>
#include <cuda_fp16.h>
#include <math.h>

#define NN 8192
#define NB 32
#define NG 256
#define NE 65536
#define DK 512
#define HH 32
#define VB 2048
#define VF 512
#define EPS 1e-5f

// ---------------- device scratch ----------------
__device__ float g_sB[NN], g_sF[NN];
__device__ __half2 g_vnB[NN * VB / 2];   // normalized visual_body fp16 (32 MB)
__device__ __half2 g_vnF[NN * VF / 2];   // normalized visual_face fp16 (8 MB)
__device__ float g_P0[DK], g_P1[DK];
__device__ float g_M1[DK], g_M2[DK], g_M3[DK];
__device__ float g_cst[12];
// sync state (reset by last block each launch)
__device__ int g_flag0 = 0;
__device__ int g_fNB[1024];
__device__ int g_fNF[1024];
__device__ int g_fA[1024];
__device__ int g_done = 0;

__device__ __forceinline__ float warpSum(float v) {
    #pragma unroll
    for (int o = 16; o; o >>= 1) v += __shfl_xor_sync(0xFFFFFFFFu, v, o);
    return v;
}

__device__ __forceinline__ int vload(const int* p) {
    return *(const volatile int*)p;
}

// ---------------- grid layout (256 threads per block) ----------------
// 0                        : precompute constants -> g_flag0
// [1, 1+1024)              : body norm, publish g_fNB
// [1025, 1025+1024)        : face norm, publish g_fNF
// [2049, 2049+1024)        : attention+node (spin g_flag0), publish g_fA
// [3073, 3073+8192)        : body edges (warp/edge, spin flags)
// [11265, 11265+4096)      : face edges (half-warp/edge, spin flags)
#define BLK_PRE   0
#define BLK_NB    1
#define BLK_NF    (BLK_NB + 1024)
#define BLK_ATTN  (BLK_NF + 1024)
#define BLK_EB    (BLK_ATTN + 1024)
#define BLK_EF    (BLK_EB + 8192)
#define GRID_TOTAL (BLK_EF + 4096)

__global__ __launch_bounds__(256, 6)
void mega_kernel(const float* __restrict__ visB, const float* __restrict__ visF,
                 const float* __restrict__ x,
                 const float* __restrict__ ln_g, const float* __restrict__ ln_b,
                 const float* __restrict__ prelu_a,
                 const float* __restrict__ Wq, const float* __restrict__ Wk,
                 const float* __restrict__ Wv,
                 const float* __restrict__ mlp_W, const float* __restrict__ mlp_b,
                 const float* __restrict__ np_W, const float* __restrict__ np_b,
                 const float* __restrict__ body_W, const float* __restrict__ body_b,
                 const float* __restrict__ face_W, const float* __restrict__ face_b,
                 const float* __restrict__ pb_W, const float* __restrict__ pb_b,
                 const float* __restrict__ pf_W, const float* __restrict__ pf_b,
                 const int* __restrict__ eiB, const int* __restrict__ eiF,
                 float* __restrict__ out) {
    int b = blockIdx.x;
    int t = threadIdx.x;
    int lane = t & 31;
    int warp = t >> 5;

    int my_flag_idx = -1;       // producer flag to publish in epilogue
    int* my_flag_arr = 0;

    if (b == BLK_PRE) {
        // ---------------- precompute constants (256 threads, 2 dims each) ----------------
        __shared__ float sh_u2[HH], sh_u3[HH], sh_np[HH];
        __shared__ float sh_part[8][9];
        __shared__ float sh_res[12];
        int k1 = t, k2 = t + 256;

        if (t < HH) {
            float a2 = 0.f, a3 = 0.f;
            #pragma unroll
            for (int j = 0; j < HH; ++j) {
                a2 += body_W[t * HH + j] * pb_W[j];
                a3 += face_W[t * HH + j] * pf_W[j];
            }
            sh_u2[t] = a2;
            sh_u3[t] = a3;
            sh_np[t] = np_W[t];
        }

        float wq0a = Wq[k1], wq0b = Wq[k2], wq1a = Wq[DK + k1], wq1b = Wq[DK + k2];
        float wk0a = Wk[k1], wk0b = Wk[k2], wk1a = Wk[DK + k1], wk1b = Wk[DK + k2];
        float wv0a = Wv[k1], wv0b = Wv[k2], wv1a = Wv[DK + k1], wv1b = Wv[DK + k2];

        float v0 = warpSum(wq0a * wk0a + wq0b * wk0b);
        float v1 = warpSum(wq0a * wk1a + wq0b * wk1b);
        float v2 = warpSum(wq1a * wk0a + wq1b * wk0b);
        float v3 = warpSum(wq1a * wk1a + wq1b * wk1b);
        float v4 = warpSum(wv0a + wv0b);
        float v5 = warpSum(wv1a + wv1b);
        float v6 = warpSum(wv0a * wv0a + wv0b * wv0b);
        float v7 = warpSum(wv0a * wv1a + wv0b * wv1b);
        float v8 = warpSum(wv1a * wv1a + wv1b * wv1b);
        if (lane == 0) {
            sh_part[warp][0] = v0; sh_part[warp][1] = v1; sh_part[warp][2] = v2;
            sh_part[warp][3] = v3; sh_part[warp][4] = v4; sh_part[warp][5] = v5;
            sh_part[warp][6] = v6; sh_part[warp][7] = v7; sh_part[warp][8] = v8;
        }
        __syncthreads();

        if (warp == 0) {
            float mb = mlp_b[lane];
            float b1 = warpSum(mb * sh_np[lane]);
            float b2 = warpSum(mb * sh_u2[lane]);
            float b3 = warpSum(mb * sh_u3[lane]);
            float vBv = warpSum(body_b[lane] * pb_W[lane]);
            float vFv = warpSum(face_b[lane] * pf_W[lane]);
            if (lane == 0) {
                float r[9];
                #pragma unroll
                for (int i = 0; i < 9; ++i) {
                    float s = 0.f;
                    #pragma unroll
                    for (int w = 0; w < 8; ++w) s += sh_part[w][i];
                    r[i] = s;
                }
                float m0 = r[4] / (float)DK, m1 = r[5] / (float)DK;
                sh_res[0] = r[0]; sh_res[1] = r[1]; sh_res[2] = r[2]; sh_res[3] = r[3];
                sh_res[4] = r[6] / (float)DK - m0 * m0;
                sh_res[5] = r[7] / (float)DK - m0 * m1;
                sh_res[6] = r[8] / (float)DK - m1 * m1;
                sh_res[7] = b1 + np_b[0] + pb_b[0] + pf_b[0];
                sh_res[8] = b2 + vBv;
                sh_res[9] = b3 + vFv;
                sh_res[10] = m0;
                sh_res[11] = m1;
            }
        }
        __syncthreads();

        if (t < 12) g_cst[t] = sh_res[t];
        g_P0[k1] = wv0a - sh_res[10];
        g_P0[k2] = wv0b - sh_res[10];
        g_P1[k1] = wv1a - sh_res[11];
        g_P1[k2] = wv1b - sh_res[11];

        float a1a = 0.f, a2a = 0.f, a3a = 0.f, a1b = 0.f, a2b = 0.f, a3b = 0.f;
        #pragma unroll
        for (int l = 0; l < HH; ++l) {
            float wa = mlp_W[k1 * HH + l];
            float wb = mlp_W[k2 * HH + l];
            float un = sh_np[l], u2 = sh_u2[l], u3 = sh_u3[l];
            a1a += wa * un; a2a += wa * u2; a3a += wa * u3;
            a1b += wb * un; a2b += wb * u2; a3b += wb * u3;
        }
        g_M1[k1] = a1a; g_M2[k1] = a2a; g_M3[k1] = a3a;
        g_M1[k2] = a1b; g_M2[k2] = a2b; g_M3[k2] = a3b;

        my_flag_arr = &g_flag0;
        my_flag_idx = 0;
    } else if (b < BLK_NF) {
        // ---------------- body norm: warp per row, two-pass (low regs) ----------------
        int nb = b - BLK_NB;             // 0..1023
        int row = nb * 8 + warp;
        const float4* v = reinterpret_cast<const float4*>(visB) + (size_t)row * (VB / 4) + lane;
        float acc = 0.f;
        #pragma unroll 4
        for (int i = 0; i < 16; ++i) {
            float4 p = v[i * 32];
            acc += p.x * p.x + p.y * p.y + p.z * p.z + p.w * p.w;
        }
        acc = warpSum(acc);
        float rs = rsqrtf(acc + 1e-8f);
        uint2* o = reinterpret_cast<uint2*>(g_vnB) + (size_t)row * (VB / 4) + lane;
        #pragma unroll 4
        for (int i = 0; i < 16; ++i) {
            float4 p = v[i * 32];     // L1 hit
            __half2 h0 = __floats2half2_rn(p.x * rs, p.y * rs);
            __half2 h1 = __floats2half2_rn(p.z * rs, p.w * rs);
            uint2 u;
            u.x = *reinterpret_cast<unsigned*>(&h0);
            u.y = *reinterpret_cast<unsigned*>(&h1);
            o[i * 32] = u;
        }
        my_flag_arr = g_fNB;
        my_flag_idx = nb;                // covers rows nb*8 .. nb*8+7
    } else if (b < BLK_ATTN) {
        // ---------------- face norm: warp per row, two-pass ----------------
        int nf = b - BLK_NF;             // 0..1023
        int row = nf * 8 + warp;
        const float4* v = reinterpret_cast<const float4*>(visF) + (size_t)row * (VF / 4) + lane;
        float acc = 0.f;
        #pragma unroll
        for (int i = 0; i < 4; ++i) {
            float4 p = v[i * 32];
            acc += p.x * p.x + p.y * p.y + p.z * p.z + p.w * p.w;
        }
        acc = warpSum(acc);
        float rs = rsqrtf(acc + 1e-8f);
        uint2* o = reinterpret_cast<uint2*>(g_vnF) + (size_t)row * (VF / 4) + lane;
        #pragma unroll
        for (int i = 0; i < 4; ++i) {
            float4 p = v[i * 32];     // L1 hit
            __half2 h0 = __floats2half2_rn(p.x * rs, p.y * rs);
            __half2 h1 = __floats2half2_rn(p.z * rs, p.w * rs);
            uint2 u;
            u.x = *reinterpret_cast<unsigned*>(&h0);
            u.y = *reinterpret_cast<unsigned*>(&h1);
            o[i * 32] = u;
        }
        my_flag_arr = g_fNF;
        my_flag_idx = nf;
    } else if (b < BLK_EB) {
        // ---------------- attention + node stage ----------------
        __shared__ float sa[NG], sb[NG];
        int idx = b - BLK_ATTN;          // 0..1023
        int g = idx >> 5;
        int bi = idx & 31;
        int node = g * NG + t;
        sa[t] = x[2 * node];
        sb[t] = x[2 * node + 1];
        if (t == 0) {
            while (vload(&g_flag0) == 0) __nanosleep(32);
        }
        __syncthreads();
        __threadfence();

        float g00 = g_cst[0], g01 = g_cst[1], g10 = g_cst[2], g11 = g_cst[3];
        const float inv = 0.04419417382415922f;
        int i = bi * 8 + warp;

        float ai = sa[i], bi2 = sb[i];
        float alpha = (ai * g00 + bi2 * g10) * inv;
        float beta  = (ai * g01 + bi2 * g11) * inv;
        float m = -1e30f;
        #pragma unroll
        for (int j = lane; j < NG; j += 32)
            m = fmaxf(m, alpha * sa[j] + beta * sb[j]);
        #pragma unroll
        for (int o = 16; o; o >>= 1) m = fmaxf(m, __shfl_xor_sync(0xFFFFFFFFu, m, o));
        float s = 0.f, sA = 0.f, sBv = 0.f;
        #pragma unroll
        for (int j = lane; j < NG; j += 32) {
            float e = __expf(alpha * sa[j] + beta * sb[j] - m);
            s += e; sA += e * sa[j]; sBv += e * sb[j];
        }
        s = warpSum(s); sA = warpSum(sA); sBv = warpSum(sBv);
        float c = sA / s, d = sBv / s;

        float s00 = g_cst[4], s01 = g_cst[5], s11 = g_cst[6];
        float var = c * c * s00 + 2.f * c * d * s01 + d * d * s11;
        float rstd = rsqrtf(var + EPS);
        float a = prelu_a[0];
        float acc1 = 0.f, acc2 = 0.f, acc3 = 0.f;
        #pragma unroll 4
        for (int k = lane; k < DK; k += 32) {
            float z = (c * g_P0[k] + d * g_P1[k]) * rstd;
            float tv = z * ln_g[k] + ln_b[k];
            tv = tv >= 0.f ? tv : a * tv;
            acc1 += tv * g_M1[k];
            acc2 += tv * g_M2[k];
            acc3 += tv * g_M3[k];
        }
        acc1 = warpSum(acc1); acc2 = warpSum(acc2); acc3 = warpSum(acc3);
        if (lane == 0) {
            int n = g * NG + i;
            out[n]  = acc1 + g_cst[7];
            g_sB[n] = acc2 + g_cst[8];
            g_sF[n] = acc3 + g_cst[9];
        }
        my_flag_arr = g_fA;
        my_flag_idx = idx;               // covers nodes idx*8 .. idx*8+7
    } else if (b < BLK_EF) {
        // ---------------- body edges: warp per edge ----------------
        int e = (b - BLK_EB) * 8 + warp;
        int src = eiB[e], dst = eiB[NE + e];
        {
            const int* f0 = &g_fNB[src >> 3];
            const int* f1 = &g_fNB[dst >> 3];
            const int* f2 = &g_fA[src >> 3];
            const int* f3 = &g_fA[dst >> 3];
            while (!(vload(f0) & vload(f1) & vload(f2) & vload(f3))) __nanosleep(64);
            __threadfence();
        }
        const int4* a = reinterpret_cast<const int4*>(g_vnB) + (size_t)src * (VB / 8) + lane;
        const int4* bb = reinterpret_cast<const int4*>(g_vnB) + (size_t)dst * (VB / 8) + lane;
        int4 ra[8], rb[8];
        #pragma unroll
        for (int i = 0; i < 8; ++i) ra[i] = a[i * 32];
        #pragma unroll
        for (int i = 0; i < 8; ++i) rb[i] = bb[i * 32];
        float acc0 = 0.f, acc1 = 0.f;
        #pragma unroll
        for (int i = 0; i < 8; ++i) {
            const __half2* ha = reinterpret_cast<const __half2*>(&ra[i]);
            const __half2* hb = reinterpret_cast<const __half2*>(&rb[i]);
            #pragma unroll
            for (int u = 0; u < 4; ++u) {
                float2 fa = __half22float2(ha[u]);
                float2 fb = __half22float2(hb[u]);
                acc0 += fa.x * fb.x;
                acc1 += fa.y * fb.y;
            }
        }
        float acc = warpSum(acc0 + acc1);
        if (lane == 0) atomicAdd(&out[dst], acc * g_sB[src]);
    } else {
        // ---------------- face edges: half-warp per edge ----------------
        int fw = (b - BLK_EF) * 8 + warp;
        int e = fw * 2 + (lane >> 4);
        int hl = lane & 15;
        int src = eiF[e], dst = eiF[NE + e];
        {
            const int* f0 = &g_fNF[src >> 3];
            const int* f1 = &g_fNF[dst >> 3];
            const int* f2 = &g_fA[src >> 3];
            const int* f3 = &g_fA[dst >> 3];
            while (true) {
                int ok = vload(f0) & vload(f1) & vload(f2) & vload(f3);
                if (__all_sync(0xFFFFFFFFu, ok)) break;
                __nanosleep(64);
            }
            __threadfence();
        }
        const int4* a = reinterpret_cast<const int4*>(g_vnF) + (size_t)src * (VF / 8) + hl;
        const int4* bb = reinterpret_cast<const int4*>(g_vnF) + (size_t)dst * (VF / 8) + hl;
        int4 ra[4], rb[4];
        #pragma unroll
        for (int i = 0; i < 4; ++i) ra[i] = a[i * 16];
        #pragma unroll
        for (int i = 0; i < 4; ++i) rb[i] = bb[i * 16];
        float acc0 = 0.f, acc1 = 0.f;
        #pragma unroll
        for (int i = 0; i < 4; ++i) {
            const __half2* ha = reinterpret_cast<const __half2*>(&ra[i]);
            const __half2* hb = reinterpret_cast<const __half2*>(&rb[i]);
            #pragma unroll
            for (int u = 0; u < 4; ++u) {
                float2 fa = __half22float2(ha[u]);
                float2 fb = __half22float2(hb[u]);
                acc0 += fa.x * fb.x;
                acc1 += fa.y * fb.y;
            }
        }
        float acc = acc0 + acc1;
        #pragma unroll
        for (int o = 8; o; o >>= 1) acc += __shfl_xor_sync(0xFFFFFFFFu, acc, o);
        if (hl == 0) atomicAdd(&out[dst], acc * g_sF[src]);
    }

    // ---------------- epilogue: publish flag, done counter, last block resets ----------------
    __shared__ int sh_last;
    __threadfence();
    __syncthreads();
    if (t == 0) {
        if (my_flag_idx >= 0) {
            *(volatile int*)&my_flag_arr[my_flag_idx] = 1;   // release (fenced above)
        }
        int d = atomicAdd(&g_done, 1);
        sh_last = (d == GRID_TOTAL - 1) ? 1 : 0;
    }
    __syncthreads();
    if (sh_last) {
        for (int i = t; i < 1024; i += 256) {
            g_fNB[i] = 0;
            g_fNF[i] = 0;
            g_fA[i] = 0;
        }
        if (t == 0) {
            g_flag0 = 0;
            __threadfence();
            g_done = 0;
        }
    }
}

// ---------------- launch ----------------
extern "C" void kernel_launch(void* const* d_in, const int* in_sizes, int n_in,
                              void* d_out, int out_size) {
    const float* x           = (const float*)d_in[0];
    const float* visual_body = (const float*)d_in[1];
    const float* visual_face = (const float*)d_in[2];
    const float* Wq          = (const float*)d_in[3];
    const float* Wk          = (const float*)d_in[4];
    const float* Wv          = (const float*)d_in[5];
    const float* ln_g        = (const float*)d_in[6];
    const float* ln_b        = (const float*)d_in[7];
    const float* prelu_a     = (const float*)d_in[8];
    const float* mlp_W       = (const float*)d_in[9];
    const float* mlp_b       = (const float*)d_in[10];
    const float* np_W        = (const float*)d_in[11];
    const float* np_b        = (const float*)d_in[12];
    const float* body_W      = (const float*)d_in[13];
    const float* body_b      = (const float*)d_in[14];
    const float* face_W      = (const float*)d_in[15];
    const float* face_b      = (const float*)d_in[16];
    const float* pb_W        = (const float*)d_in[17];
    const float* pb_b        = (const float*)d_in[18];
    const float* pf_W        = (const float*)d_in[19];
    const float* pf_b        = (const float*)d_in[20];
    const int*   ei_body     = (const int*)d_in[21];
    const int*   ei_face     = (const int*)d_in[22];
    float* out = (float*)d_out;

    mega_kernel<<<GRID_TOTAL, 256>>>(
        visual_body, visual_face, x, ln_g, ln_b, prelu_a,
        Wq, Wk, Wv, mlp_W, mlp_b, np_W, np_b,
        body_W, body_b, face_W, face_b, pb_W, pb_b, pf_W, pf_b,
        ei_body, ei_face, out);
}

// round 11
// speedup vs baseline: 1.9115x; 1.4301x over previous
#include <cuda_runtime.h>
#include <cuda_fp16.h>
#include <math.h>

#define NN 8192
#define NB 32
#define NG 256
#define NE 65536
#define DK 512
#define HH 32
#define VB 2048
#define VF 512
#define EPS 1e-5f

// ---------------- device scratch ----------------
__device__ float g_sB[NN], g_sF[NN];
__device__ __half2 g_vnB[NN * VB / 2];   // normalized visual_body fp16 (32 MB)
__device__ __half2 g_vnF[NN * VF / 2];   // normalized visual_face fp16 (8 MB)
__device__ float g_P0[DK], g_P1[DK];
__device__ float g_M1[DK], g_M2[DK], g_M3[DK];
__device__ float g_cst[12];
__device__ float g_pad_[32];
__device__ volatile int g_flag = 0;      // constants-ready flag (reset by edge_kernel)

__device__ __forceinline__ float warpSum(float v) {
    #pragma unroll
    for (int o = 16; o; o >>= 1) v += __shfl_xor_sync(0xFFFFFFFFu, v, o);
    return v;
}

// ---------------- merged kernel: precompute + norms + attn_node ----------------
// grid layout (256 threads each):
//   block 0                 : precompute constants, raise g_flag
//   [1, 1+1024)             : body norm (warp per row, two-pass)
//   [1025, 1025+1024)       : face norm (warp per row, two-pass)
//   [2049, 2049+1024)       : attention + node stage (spin g_flag)
#define BLK_PRE   0
#define BLK_NB    1
#define BLK_NF    (BLK_NB + 1024)
#define BLK_ATTN  (BLK_NF + 1024)
#define GRID_K1   (BLK_ATTN + 1024)

__global__ __launch_bounds__(256, 6)
void norm_attn_kernel(const float* __restrict__ visB, const float* __restrict__ visF,
                      const float* __restrict__ x,
                      const float* __restrict__ ln_g, const float* __restrict__ ln_b,
                      const float* __restrict__ prelu_a,
                      const float* __restrict__ Wq, const float* __restrict__ Wk,
                      const float* __restrict__ Wv,
                      const float* __restrict__ mlp_W, const float* __restrict__ mlp_b,
                      const float* __restrict__ np_W, const float* __restrict__ np_b,
                      const float* __restrict__ body_W, const float* __restrict__ body_b,
                      const float* __restrict__ face_W, const float* __restrict__ face_b,
                      const float* __restrict__ pb_W, const float* __restrict__ pb_b,
                      const float* __restrict__ pf_W, const float* __restrict__ pf_b,
                      float* __restrict__ out) {
    int b = blockIdx.x;
    int t = threadIdx.x;
    int lane = t & 31;
    int warp = t >> 5;

    if (b == BLK_PRE) {
        // ---------------- precompute constants (256 threads, 2 dims each) ----------------
        __shared__ float sh_u2[HH], sh_u3[HH], sh_np[HH];
        __shared__ float sh_part[8][9];
        __shared__ float sh_res[12];
        int k1 = t, k2 = t + 256;

        if (t < HH) {
            float a2 = 0.f, a3 = 0.f;
            #pragma unroll
            for (int j = 0; j < HH; ++j) {
                a2 += body_W[t * HH + j] * pb_W[j];
                a3 += face_W[t * HH + j] * pf_W[j];
            }
            sh_u2[t] = a2;
            sh_u3[t] = a3;
            sh_np[t] = np_W[t];
        }

        float wq0a = Wq[k1], wq0b = Wq[k2], wq1a = Wq[DK + k1], wq1b = Wq[DK + k2];
        float wk0a = Wk[k1], wk0b = Wk[k2], wk1a = Wk[DK + k1], wk1b = Wk[DK + k2];
        float wv0a = Wv[k1], wv0b = Wv[k2], wv1a = Wv[DK + k1], wv1b = Wv[DK + k2];

        float v0 = warpSum(wq0a * wk0a + wq0b * wk0b);
        float v1 = warpSum(wq0a * wk1a + wq0b * wk1b);
        float v2 = warpSum(wq1a * wk0a + wq1b * wk0b);
        float v3 = warpSum(wq1a * wk1a + wq1b * wk1b);
        float v4 = warpSum(wv0a + wv0b);
        float v5 = warpSum(wv1a + wv1b);
        float v6 = warpSum(wv0a * wv0a + wv0b * wv0b);
        float v7 = warpSum(wv0a * wv1a + wv0b * wv1b);
        float v8 = warpSum(wv1a * wv1a + wv1b * wv1b);
        if (lane == 0) {
            sh_part[warp][0] = v0; sh_part[warp][1] = v1; sh_part[warp][2] = v2;
            sh_part[warp][3] = v3; sh_part[warp][4] = v4; sh_part[warp][5] = v5;
            sh_part[warp][6] = v6; sh_part[warp][7] = v7; sh_part[warp][8] = v8;
        }
        __syncthreads();

        if (warp == 0) {
            float mb = mlp_b[lane];
            float b1 = warpSum(mb * sh_np[lane]);
            float b2 = warpSum(mb * sh_u2[lane]);
            float b3 = warpSum(mb * sh_u3[lane]);
            float vBv = warpSum(body_b[lane] * pb_W[lane]);
            float vFv = warpSum(face_b[lane] * pf_W[lane]);
            if (lane == 0) {
                float r[9];
                #pragma unroll
                for (int i = 0; i < 9; ++i) {
                    float s = 0.f;
                    #pragma unroll
                    for (int w = 0; w < 8; ++w) s += sh_part[w][i];
                    r[i] = s;
                }
                float m0 = r[4] / (float)DK, m1 = r[5] / (float)DK;
                sh_res[0] = r[0]; sh_res[1] = r[1]; sh_res[2] = r[2]; sh_res[3] = r[3];
                sh_res[4] = r[6] / (float)DK - m0 * m0;
                sh_res[5] = r[7] / (float)DK - m0 * m1;
                sh_res[6] = r[8] / (float)DK - m1 * m1;
                sh_res[7] = b1 + np_b[0] + pb_b[0] + pf_b[0];
                sh_res[8] = b2 + vBv;
                sh_res[9] = b3 + vFv;
                sh_res[10] = m0;
                sh_res[11] = m1;
            }
        }
        __syncthreads();

        if (t < 12) g_cst[t] = sh_res[t];
        g_P0[k1] = wv0a - sh_res[10];
        g_P0[k2] = wv0b - sh_res[10];
        g_P1[k1] = wv1a - sh_res[11];
        g_P1[k2] = wv1b - sh_res[11];

        float a1a = 0.f, a2a = 0.f, a3a = 0.f, a1b = 0.f, a2b = 0.f, a3b = 0.f;
        #pragma unroll
        for (int l = 0; l < HH; ++l) {
            float wa = mlp_W[k1 * HH + l];
            float wb = mlp_W[k2 * HH + l];
            float un = sh_np[l], u2 = sh_u2[l], u3 = sh_u3[l];
            a1a += wa * un; a2a += wa * u2; a3a += wa * u3;
            a1b += wb * un; a2b += wb * u2; a3b += wb * u3;
        }
        g_M1[k1] = a1a; g_M2[k1] = a2a; g_M3[k1] = a3a;
        g_M1[k2] = a1b; g_M2[k2] = a2b; g_M3[k2] = a3b;

        __threadfence();
        __syncthreads();
        if (t == 0) g_flag = 1;
    } else if (b < BLK_NF) {
        // ---------------- body norm: warp per row, two-pass (low regs) ----------------
        int row = ((b - BLK_NB) * 256 + t) >> 5;
        const float4* v = reinterpret_cast<const float4*>(visB) + (size_t)row * (VB / 4) + lane;
        float acc = 0.f;
        #pragma unroll 4
        for (int i = 0; i < 16; ++i) {
            float4 p = v[i * 32];
            acc += p.x * p.x + p.y * p.y + p.z * p.z + p.w * p.w;
        }
        acc = warpSum(acc);
        float rs = rsqrtf(acc + 1e-8f);
        uint2* o = reinterpret_cast<uint2*>(g_vnB) + (size_t)row * (VB / 4) + lane;
        #pragma unroll 4
        for (int i = 0; i < 16; ++i) {
            float4 p = v[i * 32];     // L1 hit
            __half2 h0 = __floats2half2_rn(p.x * rs, p.y * rs);
            __half2 h1 = __floats2half2_rn(p.z * rs, p.w * rs);
            uint2 u;
            u.x = *reinterpret_cast<unsigned*>(&h0);
            u.y = *reinterpret_cast<unsigned*>(&h1);
            o[i * 32] = u;
        }
    } else if (b < BLK_ATTN) {
        // ---------------- face norm: warp per row, two-pass ----------------
        int row = ((b - BLK_NF) * 256 + t) >> 5;
        const float4* v = reinterpret_cast<const float4*>(visF) + (size_t)row * (VF / 4) + lane;
        float acc = 0.f;
        #pragma unroll
        for (int i = 0; i < 4; ++i) {
            float4 p = v[i * 32];
            acc += p.x * p.x + p.y * p.y + p.z * p.z + p.w * p.w;
        }
        acc = warpSum(acc);
        float rs = rsqrtf(acc + 1e-8f);
        uint2* o = reinterpret_cast<uint2*>(g_vnF) + (size_t)row * (VF / 4) + lane;
        #pragma unroll
        for (int i = 0; i < 4; ++i) {
            float4 p = v[i * 32];     // L1 hit
            __half2 h0 = __floats2half2_rn(p.x * rs, p.y * rs);
            __half2 h1 = __floats2half2_rn(p.z * rs, p.w * rs);
            uint2 u;
            u.x = *reinterpret_cast<unsigned*>(&h0);
            u.y = *reinterpret_cast<unsigned*>(&h1);
            o[i * 32] = u;
        }
    } else {
        // ---------------- attention + node stage (spin g_flag, dispatched last) ----------------
        __shared__ float sa[NG], sb[NG];
        int idx = b - BLK_ATTN;
        int g = idx >> 5;
        int bi = idx & 31;
        int node = g * NG + t;
        sa[t] = x[2 * node];
        sb[t] = x[2 * node + 1];
        if (t == 0) {
            while (g_flag == 0) {}
        }
        __syncthreads();
        __threadfence();

        float g00 = g_cst[0], g01 = g_cst[1], g10 = g_cst[2], g11 = g_cst[3];
        const float inv = 0.04419417382415922f;
        int i = bi * 8 + warp;

        float ai = sa[i], bi2 = sb[i];
        float alpha = (ai * g00 + bi2 * g10) * inv;
        float beta  = (ai * g01 + bi2 * g11) * inv;
        float m = -1e30f;
        #pragma unroll
        for (int j = lane; j < NG; j += 32)
            m = fmaxf(m, alpha * sa[j] + beta * sb[j]);
        #pragma unroll
        for (int o = 16; o; o >>= 1) m = fmaxf(m, __shfl_xor_sync(0xFFFFFFFFu, m, o));
        float s = 0.f, sA = 0.f, sBv = 0.f;
        #pragma unroll
        for (int j = lane; j < NG; j += 32) {
            float e = __expf(alpha * sa[j] + beta * sb[j] - m);
            s += e; sA += e * sa[j]; sBv += e * sb[j];
        }
        s = warpSum(s); sA = warpSum(sA); sBv = warpSum(sBv);
        float c = sA / s, d = sBv / s;

        float s00 = g_cst[4], s01 = g_cst[5], s11 = g_cst[6];
        float var = c * c * s00 + 2.f * c * d * s01 + d * d * s11;
        float rstd = rsqrtf(var + EPS);
        float a = prelu_a[0];
        float acc1 = 0.f, acc2 = 0.f, acc3 = 0.f;
        #pragma unroll 4
        for (int k = lane; k < DK; k += 32) {
            float z = (c * g_P0[k] + d * g_P1[k]) * rstd;
            float tv = z * ln_g[k] + ln_b[k];
            tv = tv >= 0.f ? tv : a * tv;
            acc1 += tv * g_M1[k];
            acc2 += tv * g_M2[k];
            acc3 += tv * g_M3[k];
        }
        acc1 = warpSum(acc1); acc2 = warpSum(acc2); acc3 = warpSum(acc3);
        if (lane == 0) {
            int n = g * NG + i;
            out[n]  = acc1 + g_cst[7];
            g_sB[n] = acc2 + g_cst[8];
            g_sF[n] = acc3 + g_cst[9];
        }
    }
}

// ---------------- K_edge: merged body+face, deep prefetch (proven 38 us) ----------------
#define EDGE_TPB 128
#define BODY_WARPS NE                 // 65536 warps
#define FACE_WARPS (NE / 2)           // 32768 warps
#define BODY_BLOCKS (BODY_WARPS * 32 / EDGE_TPB)   // 16384
#define FACE_BLOCKS (FACE_WARPS * 32 / EDGE_TPB)   // 8192

__global__ void edge_kernel(const int* __restrict__ eiB, const int* __restrict__ eiF,
                            float* __restrict__ out) {
    // reset the constants flag for the next graph replay (stream-ordered after all readers)
    if (blockIdx.x == 0 && threadIdx.x == 0) g_flag = 0;

    int gw = (blockIdx.x * EDGE_TPB + threadIdx.x) >> 5;
    int lane = threadIdx.x & 31;

    if (gw < BODY_WARPS) {
        int e = gw;
        int src = eiB[e], dst = eiB[NE + e];
        const int4* a = reinterpret_cast<const int4*>(g_vnB) + (size_t)src * (VB / 8) + lane;
        const int4* b = reinterpret_cast<const int4*>(g_vnB) + (size_t)dst * (VB / 8) + lane;
        int4 ra[8], rb[8];
        #pragma unroll
        for (int i = 0; i < 8; ++i) ra[i] = a[i * 32];
        #pragma unroll
        for (int i = 0; i < 8; ++i) rb[i] = b[i * 32];
        float acc0 = 0.f, acc1 = 0.f;
        #pragma unroll
        for (int i = 0; i < 8; ++i) {
            const __half2* ha = reinterpret_cast<const __half2*>(&ra[i]);
            const __half2* hb = reinterpret_cast<const __half2*>(&rb[i]);
            #pragma unroll
            for (int u = 0; u < 4; ++u) {
                float2 fa = __half22float2(ha[u]);
                float2 fb = __half22float2(hb[u]);
                acc0 += fa.x * fb.x;
                acc1 += fa.y * fb.y;
            }
        }
        float acc = warpSum(acc0 + acc1);
        if (lane == 0) atomicAdd(&out[dst], acc * g_sB[src]);
    } else {
        int e = (gw - BODY_WARPS) * 2 + (lane >> 4);
        int hl = lane & 15;
        int src = eiF[e], dst = eiF[NE + e];
        const int4* a = reinterpret_cast<const int4*>(g_vnF) + (size_t)src * (VF / 8) + hl;
        const int4* b = reinterpret_cast<const int4*>(g_vnF) + (size_t)dst * (VF / 8) + hl;
        int4 ra[4], rb[4];
        #pragma unroll
        for (int i = 0; i < 4; ++i) ra[i] = a[i * 16];
        #pragma unroll
        for (int i = 0; i < 4; ++i) rb[i] = b[i * 16];
        float acc0 = 0.f, acc1 = 0.f;
        #pragma unroll
        for (int i = 0; i < 4; ++i) {
            const __half2* ha = reinterpret_cast<const __half2*>(&ra[i]);
            const __half2* hb = reinterpret_cast<const __half2*>(&rb[i]);
            #pragma unroll
            for (int u = 0; u < 4; ++u) {
                float2 fa = __half22float2(ha[u]);
                float2 fb = __half22float2(hb[u]);
                acc0 += fa.x * fb.x;
                acc1 += fa.y * fb.y;
            }
        }
        float acc = acc0 + acc1;
        #pragma unroll
        for (int o = 8; o; o >>= 1) acc += __shfl_xor_sync(0xFFFFFFFFu, acc, o);
        if (hl == 0) atomicAdd(&out[dst], acc * g_sF[src]);
    }
}

// ---------------- launch ----------------
extern "C" void kernel_launch(void* const* d_in, const int* in_sizes, int n_in,
                              void* d_out, int out_size) {
    const float* x           = (const float*)d_in[0];
    const float* visual_body = (const float*)d_in[1];
    const float* visual_face = (const float*)d_in[2];
    const float* Wq          = (const float*)d_in[3];
    const float* Wk          = (const float*)d_in[4];
    const float* Wv          = (const float*)d_in[5];
    const float* ln_g        = (const float*)d_in[6];
    const float* ln_b        = (const float*)d_in[7];
    const float* prelu_a     = (const float*)d_in[8];
    const float* mlp_W       = (const float*)d_in[9];
    const float* mlp_b       = (const float*)d_in[10];
    const float* np_W        = (const float*)d_in[11];
    const float* np_b        = (const float*)d_in[12];
    const float* body_W      = (const float*)d_in[13];
    const float* body_b      = (const float*)d_in[14];
    const float* face_W      = (const float*)d_in[15];
    const float* face_b      = (const float*)d_in[16];
    const float* pb_W        = (const float*)d_in[17];
    const float* pb_b        = (const float*)d_in[18];
    const float* pf_W        = (const float*)d_in[19];
    const float* pf_b        = (const float*)d_in[20];
    const int*   ei_body     = (const int*)d_in[21];
    const int*   ei_face     = (const int*)d_in[22];
    float* out = (float*)d_out;

    norm_attn_kernel<<<GRID_K1, 256>>>(
        visual_body, visual_face, x, ln_g, ln_b, prelu_a,
        Wq, Wk, Wv, mlp_W, mlp_b, np_W, np_b,
        body_W, body_b, face_W, face_b, pb_W, pb_b, pf_W, pf_b, out);

    edge_kernel<<<BODY_BLOCKS + FACE_BLOCKS, EDGE_TPB>>>(ei_body, ei_face, out);
}

// round 12
// speedup vs baseline: 1.9575x; 1.0241x over previous
#include <cuda_runtime.h>
#include <cuda_fp16.h>
#include <math.h>

#define NN 8192
#define NB 32
#define NG 256
#define NE 65536
#define DK 512
#define HH 32
#define VB 2048
#define VF 512
#define EPS 1e-5f

// ---------------- device scratch ----------------
__device__ float g_sB[NN], g_sF[NN];
__device__ __half2 g_vnB[NN * VB / 2];   // normalized visual_body fp16 (32 MB)
__device__ __half2 g_vnF[NN * VF / 2];   // normalized visual_face fp16 (8 MB)
__device__ float g_P0[DK], g_P1[DK];
__device__ float g_M1[DK], g_M2[DK], g_M3[DK];
__device__ float g_cst[12];
__device__ float g_pad_[32];
__device__ volatile int g_flag = 0;      // constants-ready flag (reset by edge_kernel)

__device__ __forceinline__ float warpSum(float v) {
    #pragma unroll
    for (int o = 16; o; o >>= 1) v += __shfl_xor_sync(0xFFFFFFFFu, v, o);
    return v;
}

// ---------------- merged kernel: precompute + norms + attn_node ----------------
// grid layout (256 threads each):
//   block 0                    : precompute constants, raise g_flag
//   [1, 1+8192)                : body norm (BLOCK per row, single pass, low regs)
//   [8193, 8193+1024)          : face norm (warp per row, single pass)
//   [9217, 9217+1024)          : attention + node stage (spin g_flag)
#define BLK_PRE   0
#define BLK_NB    1
#define BLK_NF    (BLK_NB + NN)
#define BLK_ATTN  (BLK_NF + 1024)
#define GRID_K1   (BLK_ATTN + 1024)

__global__ __launch_bounds__(256)
void norm_attn_kernel(const float* __restrict__ visB, const float* __restrict__ visF,
                      const float* __restrict__ x,
                      const float* __restrict__ ln_g, const float* __restrict__ ln_b,
                      const float* __restrict__ prelu_a,
                      const float* __restrict__ Wq, const float* __restrict__ Wk,
                      const float* __restrict__ Wv,
                      const float* __restrict__ mlp_W, const float* __restrict__ mlp_b,
                      const float* __restrict__ np_W, const float* __restrict__ np_b,
                      const float* __restrict__ body_W, const float* __restrict__ body_b,
                      const float* __restrict__ face_W, const float* __restrict__ face_b,
                      const float* __restrict__ pb_W, const float* __restrict__ pb_b,
                      const float* __restrict__ pf_W, const float* __restrict__ pf_b,
                      float* __restrict__ out) {
    int b = blockIdx.x;
    int t = threadIdx.x;
    int lane = t & 31;
    int warp = t >> 5;

    if (b == BLK_PRE) {
        // ---------------- precompute constants (256 threads, 2 dims each) ----------------
        __shared__ float sh_u2[HH], sh_u3[HH], sh_np[HH];
        __shared__ float sh_part[8][9];
        __shared__ float sh_res[12];
        int k1 = t, k2 = t + 256;

        if (t < HH) {
            float a2 = 0.f, a3 = 0.f;
            #pragma unroll
            for (int j = 0; j < HH; ++j) {
                a2 += body_W[t * HH + j] * pb_W[j];
                a3 += face_W[t * HH + j] * pf_W[j];
            }
            sh_u2[t] = a2;
            sh_u3[t] = a3;
            sh_np[t] = np_W[t];
        }

        float wq0a = Wq[k1], wq0b = Wq[k2], wq1a = Wq[DK + k1], wq1b = Wq[DK + k2];
        float wk0a = Wk[k1], wk0b = Wk[k2], wk1a = Wk[DK + k1], wk1b = Wk[DK + k2];
        float wv0a = Wv[k1], wv0b = Wv[k2], wv1a = Wv[DK + k1], wv1b = Wv[DK + k2];

        float v0 = warpSum(wq0a * wk0a + wq0b * wk0b);
        float v1 = warpSum(wq0a * wk1a + wq0b * wk1b);
        float v2 = warpSum(wq1a * wk0a + wq1b * wk0b);
        float v3 = warpSum(wq1a * wk1a + wq1b * wk1b);
        float v4 = warpSum(wv0a + wv0b);
        float v5 = warpSum(wv1a + wv1b);
        float v6 = warpSum(wv0a * wv0a + wv0b * wv0b);
        float v7 = warpSum(wv0a * wv1a + wv0b * wv1b);
        float v8 = warpSum(wv1a * wv1a + wv1b * wv1b);
        if (lane == 0) {
            sh_part[warp][0] = v0; sh_part[warp][1] = v1; sh_part[warp][2] = v2;
            sh_part[warp][3] = v3; sh_part[warp][4] = v4; sh_part[warp][5] = v5;
            sh_part[warp][6] = v6; sh_part[warp][7] = v7; sh_part[warp][8] = v8;
        }
        __syncthreads();

        if (warp == 0) {
            float mb = mlp_b[lane];
            float b1 = warpSum(mb * sh_np[lane]);
            float b2 = warpSum(mb * sh_u2[lane]);
            float b3 = warpSum(mb * sh_u3[lane]);
            float vBv = warpSum(body_b[lane] * pb_W[lane]);
            float vFv = warpSum(face_b[lane] * pf_W[lane]);
            if (lane == 0) {
                float r[9];
                #pragma unroll
                for (int i = 0; i < 9; ++i) {
                    float s = 0.f;
                    #pragma unroll
                    for (int w = 0; w < 8; ++w) s += sh_part[w][i];
                    r[i] = s;
                }
                float m0 = r[4] / (float)DK, m1 = r[5] / (float)DK;
                sh_res[0] = r[0]; sh_res[1] = r[1]; sh_res[2] = r[2]; sh_res[3] = r[3];
                sh_res[4] = r[6] / (float)DK - m0 * m0;
                sh_res[5] = r[7] / (float)DK - m0 * m1;
                sh_res[6] = r[8] / (float)DK - m1 * m1;
                sh_res[7] = b1 + np_b[0] + pb_b[0] + pf_b[0];
                sh_res[8] = b2 + vBv;
                sh_res[9] = b3 + vFv;
                sh_res[10] = m0;
                sh_res[11] = m1;
            }
        }
        __syncthreads();

        if (t < 12) g_cst[t] = sh_res[t];
        g_P0[k1] = wv0a - sh_res[10];
        g_P0[k2] = wv0b - sh_res[10];
        g_P1[k1] = wv1a - sh_res[11];
        g_P1[k2] = wv1b - sh_res[11];

        float a1a = 0.f, a2a = 0.f, a3a = 0.f, a1b = 0.f, a2b = 0.f, a3b = 0.f;
        #pragma unroll
        for (int l = 0; l < HH; ++l) {
            float wa = mlp_W[k1 * HH + l];
            float wb = mlp_W[k2 * HH + l];
            float un = sh_np[l], u2 = sh_u2[l], u3 = sh_u3[l];
            a1a += wa * un; a2a += wa * u2; a3a += wa * u3;
            a1b += wb * un; a2b += wb * u2; a3b += wb * u3;
        }
        g_M1[k1] = a1a; g_M2[k1] = a2a; g_M3[k1] = a3a;
        g_M1[k2] = a1b; g_M2[k2] = a2b; g_M3[k2] = a3b;

        __threadfence();
        __syncthreads();
        if (t == 0) g_flag = 1;
    } else if (b < BLK_NF) {
        // ---------------- body norm: BLOCK per row, single pass, 2 float4/thread ----------------
        __shared__ float sh_w[8];
        __shared__ float sh_rs;
        int row = b - BLK_NB;
        const float4* v = reinterpret_cast<const float4*>(visB) + (size_t)row * (VB / 4);
        float4 p0 = v[t];
        float4 p1 = v[t + 256];
        float acc = p0.x * p0.x + p0.y * p0.y + p0.z * p0.z + p0.w * p0.w
                  + p1.x * p1.x + p1.y * p1.y + p1.z * p1.z + p1.w * p1.w;
        acc = warpSum(acc);
        if (lane == 0) sh_w[warp] = acc;
        __syncthreads();
        if (t == 0) {
            float s = 0.f;
            #pragma unroll
            for (int i = 0; i < 8; ++i) s += sh_w[i];
            sh_rs = rsqrtf(s + 1e-8f);
        }
        __syncthreads();
        float rs = sh_rs;
        uint2* o = reinterpret_cast<uint2*>(g_vnB) + (size_t)row * (VB / 4);
        {
            __half2 h0 = __floats2half2_rn(p0.x * rs, p0.y * rs);
            __half2 h1 = __floats2half2_rn(p0.z * rs, p0.w * rs);
            uint2 u;
            u.x = *reinterpret_cast<unsigned*>(&h0);
            u.y = *reinterpret_cast<unsigned*>(&h1);
            o[t] = u;
            h0 = __floats2half2_rn(p1.x * rs, p1.y * rs);
            h1 = __floats2half2_rn(p1.z * rs, p1.w * rs);
            u.x = *reinterpret_cast<unsigned*>(&h0);
            u.y = *reinterpret_cast<unsigned*>(&h1);
            o[t + 256] = u;
        }
    } else if (b < BLK_ATTN) {
        // ---------------- face norm: warp per row, single pass, 4 float4/lane ----------------
        int row = ((b - BLK_NF) * 256 + t) >> 5;
        const float4* v = reinterpret_cast<const float4*>(visF) + (size_t)row * (VF / 4) + lane;
        float4 r0 = v[0];
        float4 r1 = v[32];
        float4 r2 = v[64];
        float4 r3 = v[96];
        float acc = r0.x * r0.x + r0.y * r0.y + r0.z * r0.z + r0.w * r0.w
                  + r1.x * r1.x + r1.y * r1.y + r1.z * r1.z + r1.w * r1.w
                  + r2.x * r2.x + r2.y * r2.y + r2.z * r2.z + r2.w * r2.w
                  + r3.x * r3.x + r3.y * r3.y + r3.z * r3.z + r3.w * r3.w;
        acc = warpSum(acc);
        float rs = rsqrtf(acc + 1e-8f);
        uint2* o = reinterpret_cast<uint2*>(g_vnF) + (size_t)row * (VF / 4) + lane;
        uint2 u;
        __half2 h0, h1;
        h0 = __floats2half2_rn(r0.x * rs, r0.y * rs);
        h1 = __floats2half2_rn(r0.z * rs, r0.w * rs);
        u.x = *reinterpret_cast<unsigned*>(&h0);
        u.y = *reinterpret_cast<unsigned*>(&h1);
        o[0] = u;
        h0 = __floats2half2_rn(r1.x * rs, r1.y * rs);
        h1 = __floats2half2_rn(r1.z * rs, r1.w * rs);
        u.x = *reinterpret_cast<unsigned*>(&h0);
        u.y = *reinterpret_cast<unsigned*>(&h1);
        o[32] = u;
        h0 = __floats2half2_rn(r2.x * rs, r2.y * rs);
        h1 = __floats2half2_rn(r2.z * rs, r2.w * rs);
        u.x = *reinterpret_cast<unsigned*>(&h0);
        u.y = *reinterpret_cast<unsigned*>(&h1);
        o[64] = u;
        h0 = __floats2half2_rn(r3.x * rs, r3.y * rs);
        h1 = __floats2half2_rn(r3.z * rs, r3.w * rs);
        u.x = *reinterpret_cast<unsigned*>(&h0);
        u.y = *reinterpret_cast<unsigned*>(&h1);
        o[96] = u;
    } else {
        // ---------------- attention + node stage (spin g_flag, dispatched last) ----------------
        __shared__ float sa[NG], sb[NG];
        int idx = b - BLK_ATTN;
        int g = idx >> 5;
        int bi = idx & 31;
        int node = g * NG + t;
        sa[t] = x[2 * node];
        sb[t] = x[2 * node + 1];
        if (t == 0) {
            while (g_flag == 0) {}
        }
        __syncthreads();
        __threadfence();

        float g00 = g_cst[0], g01 = g_cst[1], g10 = g_cst[2], g11 = g_cst[3];
        const float inv = 0.04419417382415922f;
        int i = bi * 8 + warp;

        float ai = sa[i], bi2 = sb[i];
        float alpha = (ai * g00 + bi2 * g10) * inv;
        float beta  = (ai * g01 + bi2 * g11) * inv;
        float m = -1e30f;
        #pragma unroll
        for (int j = lane; j < NG; j += 32)
            m = fmaxf(m, alpha * sa[j] + beta * sb[j]);
        #pragma unroll
        for (int o = 16; o; o >>= 1) m = fmaxf(m, __shfl_xor_sync(0xFFFFFFFFu, m, o));
        float s = 0.f, sA = 0.f, sBv = 0.f;
        #pragma unroll
        for (int j = lane; j < NG; j += 32) {
            float e = __expf(alpha * sa[j] + beta * sb[j] - m);
            s += e; sA += e * sa[j]; sBv += e * sb[j];
        }
        s = warpSum(s); sA = warpSum(sA); sBv = warpSum(sBv);
        float c = sA / s, d = sBv / s;

        float s00 = g_cst[4], s01 = g_cst[5], s11 = g_cst[6];
        float var = c * c * s00 + 2.f * c * d * s01 + d * d * s11;
        float rstd = rsqrtf(var + EPS);
        float a = prelu_a[0];
        float acc1 = 0.f, acc2 = 0.f, acc3 = 0.f;
        #pragma unroll 4
        for (int k = lane; k < DK; k += 32) {
            float z = (c * g_P0[k] + d * g_P1[k]) * rstd;
            float tv = z * ln_g[k] + ln_b[k];
            tv = tv >= 0.f ? tv : a * tv;
            acc1 += tv * g_M1[k];
            acc2 += tv * g_M2[k];
            acc3 += tv * g_M3[k];
        }
        acc1 = warpSum(acc1); acc2 = warpSum(acc2); acc3 = warpSum(acc3);
        if (lane == 0) {
            int n = g * NG + i;
            out[n]  = acc1 + g_cst[7];
            g_sB[n] = acc2 + g_cst[8];
            g_sF[n] = acc3 + g_cst[9];
        }
    }
}

// ---------------- K_edge: merged body+face, deep prefetch (proven 38 us, unchanged) ----------------
#define EDGE_TPB 128
#define BODY_WARPS NE                 // 65536 warps
#define FACE_WARPS (NE / 2)           // 32768 warps
#define BODY_BLOCKS (BODY_WARPS * 32 / EDGE_TPB)   // 16384
#define FACE_BLOCKS (FACE_WARPS * 32 / EDGE_TPB)   // 8192

__global__ void edge_kernel(const int* __restrict__ eiB, const int* __restrict__ eiF,
                            float* __restrict__ out) {
    // reset the constants flag for the next graph replay (stream-ordered after all readers)
    if (blockIdx.x == 0 && threadIdx.x == 0) g_flag = 0;

    int gw = (blockIdx.x * EDGE_TPB + threadIdx.x) >> 5;
    int lane = threadIdx.x & 31;

    if (gw < BODY_WARPS) {
        int e = gw;
        int src = eiB[e], dst = eiB[NE + e];
        const int4* a = reinterpret_cast<const int4*>(g_vnB) + (size_t)src * (VB / 8) + lane;
        const int4* b = reinterpret_cast<const int4*>(g_vnB) + (size_t)dst * (VB / 8) + lane;
        int4 ra[8], rb[8];
        #pragma unroll
        for (int i = 0; i < 8; ++i) ra[i] = a[i * 32];
        #pragma unroll
        for (int i = 0; i < 8; ++i) rb[i] = b[i * 32];
        float acc0 = 0.f, acc1 = 0.f;
        #pragma unroll
        for (int i = 0; i < 8; ++i) {
            const __half2* ha = reinterpret_cast<const __half2*>(&ra[i]);
            const __half2* hb = reinterpret_cast<const __half2*>(&rb[i]);
            #pragma unroll
            for (int u = 0; u < 4; ++u) {
                float2 fa = __half22float2(ha[u]);
                float2 fb = __half22float2(hb[u]);
                acc0 += fa.x * fb.x;
                acc1 += fa.y * fb.y;
            }
        }
        float acc = warpSum(acc0 + acc1);
        if (lane == 0) atomicAdd(&out[dst], acc * g_sB[src]);
    } else {
        int e = (gw - BODY_WARPS) * 2 + (lane >> 4);
        int hl = lane & 15;
        int src = eiF[e], dst = eiF[NE + e];
        const int4* a = reinterpret_cast<const int4*>(g_vnF) + (size_t)src * (VF / 8) + hl;
        const int4* b = reinterpret_cast<const int4*>(g_vnF) + (size_t)dst * (VF / 8) + hl;
        int4 ra[4], rb[4];
        #pragma unroll
        for (int i = 0; i < 4; ++i) ra[i] = a[i * 16];
        #pragma unroll
        for (int i = 0; i < 4; ++i) rb[i] = b[i * 16];
        float acc0 = 0.f, acc1 = 0.f;
        #pragma unroll
        for (int i = 0; i < 4; ++i) {
            const __half2* ha = reinterpret_cast<const __half2*>(&ra[i]);
            const __half2* hb = reinterpret_cast<const __half2*>(&rb[i]);
            #pragma unroll
            for (int u = 0; u < 4; ++u) {
                float2 fa = __half22float2(ha[u]);
                float2 fb = __half22float2(hb[u]);
                acc0 += fa.x * fb.x;
                acc1 += fa.y * fb.y;
            }
        }
        float acc = acc0 + acc1;
        #pragma unroll
        for (int o = 8; o; o >>= 1) acc += __shfl_xor_sync(0xFFFFFFFFu, acc, o);
        if (hl == 0) atomicAdd(&out[dst], acc * g_sF[src]);
    }
}

// ---------------- launch ----------------
extern "C" void kernel_launch(void* const* d_in, const int* in_sizes, int n_in,
                              void* d_out, int out_size) {
    const float* x           = (const float*)d_in[0];
    const float* visual_body = (const float*)d_in[1];
    const float* visual_face = (const float*)d_in[2];
    const float* Wq          = (const float*)d_in[3];
    const float* Wk          = (const float*)d_in[4];
    const float* Wv          = (const float*)d_in[5];
    const float* ln_g        = (const float*)d_in[6];
    const float* ln_b        = (const float*)d_in[7];
    const float* prelu_a     = (const float*)d_in[8];
    const float* mlp_W       = (const float*)d_in[9];
    const float* mlp_b       = (const float*)d_in[10];
    const float* np_W        = (const float*)d_in[11];
    const float* np_b        = (const float*)d_in[12];
    const float* body_W      = (const float*)d_in[13];
    const float* body_b      = (const float*)d_in[14];
    const float* face_W      = (const float*)d_in[15];
    const float* face_b      = (const float*)d_in[16];
    const float* pb_W        = (const float*)d_in[17];
    const float* pb_b        = (const float*)d_in[18];
    const float* pf_W        = (const float*)d_in[19];
    const float* pf_b        = (const float*)d_in[20];
    const int*   ei_body     = (const int*)d_in[21];
    const int*   ei_face     = (const int*)d_in[22];
    float* out = (float*)d_out;

    norm_attn_kernel<<<GRID_K1, 256>>>(
        visual_body, visual_face, x, ln_g, ln_b, prelu_a,
        Wq, Wk, Wv, mlp_W, mlp_b, np_W, np_b,
        body_W, body_b, face_W, face_b, pb_W, pb_b, pf_W, pf_b, out);

    edge_kernel<<<BODY_BLOCKS + FACE_BLOCKS, EDGE_TPB>>>(ei_body, ei_face, out);
}